// round 14
// baseline (speedup 1.0000x reference)
#include <cuda_runtime.h>

#define NGRID 20
#define NPTS  8000           // 20^3
#define TD    39             // offsets -19..19
#define DA_MAX 7             // da^2/2 > 28 -> plane pruned
#define D2_CUT 28.0f
#define QSCALE 16777216.0f   // 2^24 fixed point (max sum ~1.8e8 < 2^31)
#define NLIVE  244           // live (ia,ib) pairs with |ia-ib| <= DA_MAX

// Scratch (no allocation allowed in kernel_launch)
__device__ int   g_accum[NPTS];             // fixed-point accumulator
                                            // (zero-init; reset by finisher)
__device__ float g_bsum[NGRID * NGRID];     // per live pair sum
__device__ int   g_done;                    // completion counter (self-reset)

// ---------------------------------------------------------------------------
// Single kernel. Conv body identical to the R13-validated version (int
// fixed-point REDG accumulation -> deterministic). After its pair, each live
// block fences + bumps g_done; the 244th (last) block runs the epilogue:
// S fold (warp 0, fixed order), dequantize+normalize 20 pts/thread from
// L2-hot g_accum, reset accumulators + counter (graph-replay safe).
// ---------------------------------------------------------------------------
__global__ void __launch_bounds__(400) kde_kernel(
    const float* __restrict__ p, const float* __restrict__ cov_inv,
    float* __restrict__ out)
{
    __shared__ __align__(16) float sT[TD * TD + 3];
    __shared__ __align__(16) float sp[NGRID * NGRID];
    __shared__ __align__(16) float sred[1600];
    __shared__ int   sflag;
    __shared__ float sS;

    const int t  = threadIdx.x;
    const int ia = blockIdx.x;
    const int ib = blockIdx.y;
    const int da = ia - ib;

    if (da < -DA_MAX || da > DA_MAX) return;   // pruned: touches nothing

    const float a00 = cov_inv[0], a01 = cov_inv[1], a02 = cov_inv[2];
    const float a11 = cov_inv[4], a12 = cov_inv[5], a22 = cov_inv[8];

    sp[t] = p[ib * 400 + t];

    if (t < 156) {     // table slab via 2-FMUL exp recurrence
        int row = t >> 2, seg = t & 3;
        float dy = (float)(row - 19);
        int   dz0 = -19 + seg * 10;
        int   cnt = (seg == 3) ? 9 : 10;
        float dx = (float)da;
        float c1 = 2.0f * (a02 * dx + a12 * dy);
        float c0 = a00 * dx * dx + 2.0f * a01 * dx * dy + a11 * dy * dy;
        float z  = (float)dz0;
        float g  = expf(-0.5f * (c0 + c1 * z + a22 * z * z));
        float r  = expf(-0.5f * (c1 + a22 * (2.0f * z + 1.0f)));
        float B  = expf(-a22);
        float* dst = &sT[row * TD + (dz0 + 19)];
        for (int i = 0; i < cnt; i++) { dst[i] = g; g *= r; r *= B; }
    }
    __syncthreads();

    const int gidx = t / 100;
    const int s    = t - gidx * 100;
    const int ja   = s / 5;
    const int ka0  = (s - ja * 5) * 4;

    float s00 = a00 - a02 * a02 / a22;
    float s01 = a01 - a02 * a12 / a22;
    float s11 = a11 - a12 * a12 / a22;
    float fx  = (float)da;
    float bq  = s01 * fx;
    float disc = bq * bq - s11 * (s00 * fx * fx - D2_CUT);
    int jb_lo = 0, jb_hi = -1;
    if (disc > 0.0f) {
        float sq  = sqrtf(disc);
        float dyl = (-bq - sq) / s11;
        float dyh = (-bq + sq) / s11;
        jb_lo = max(0,  (int)ceilf ((float)ja - dyh - 0.01f));
        jb_hi = min(19, (int)floorf((float)ja - dyl + 0.01f));
    }

    float acc0 = 0.f, acc1 = 0.f, acc2 = 0.f, acc3 = 0.f;

    for (int jb = jb_lo + gidx; jb <= jb_hi; jb += 4) {
        const float* row = &sT[(ja - jb + 19) * TD];

        float pv[20];
        {
            const float4* pr4 = reinterpret_cast<const float4*>(&sp[jb * NGRID]);
#pragma unroll
            for (int u = 0; u < 5; u++) {
                float4 v = pr4[u];
                pv[4*u] = v.x; pv[4*u+1] = v.y; pv[4*u+2] = v.z; pv[4*u+3] = v.w;
            }
        }

        float w0 = row[ka0 + 19];
        float w1 = row[ka0 + 20];
        float w2 = row[ka0 + 21];
        float w3 = row[ka0 + 22];
#pragma unroll
        for (int kb = 0; kb < 20; kb++) {
            float pvk = pv[kb];
            acc0 = fmaf(w0, pvk, acc0);
            acc1 = fmaf(w1, pvk, acc1);
            acc2 = fmaf(w2, pvk, acc2);
            acc3 = fmaf(w3, pvk, acc3);
            if (kb < 19) { w3 = w2; w2 = w1; w1 = w0; w0 = row[ka0 + 18 - kb]; }
        }
    }

    *reinterpret_cast<float4*>(&sred[gidx * 400 + s * 4]) =
        make_float4(acc0, acc1, acc2, acc3);
    __syncthreads();

    // fold jb-groups (fixed order), accumulate into fixed point
    float val = sred[t] + sred[400 + t] + sred[800 + t] + sred[1200 + t];
    atomicAdd(&g_accum[ia * 400 + t], __float2int_rn(val * QSCALE));
    __syncthreads();

    // block normalizer contribution (deterministic tree)
    sred[t] = val;
    if (t < 112) sred[400 + t] = 0.0f;
    __syncthreads();
    for (int k = 256; k > 32; k >>= 1) {
        if (t < k) sred[t] += sred[t + k];
        __syncthreads();
    }
    if (t < 32) {
        float v = sred[t] + sred[t + 32];
#pragma unroll
        for (int off = 16; off > 0; off >>= 1)
            v += __shfl_down_sync(0xffffffffu, v, off);
        if (t == 0) g_bsum[ia * NGRID + ib] = v;
    }

    // ---------------- completion: am I the last live block? ----------------
    __threadfence();          // release: accum atomics + bsum visible
    __syncthreads();
    if (t == 0) {
        int c = atomicAdd(&g_done, 1);
        sflag = (c == NLIVE - 1);
    }
    __syncthreads();
    if (!sflag) return;
    __threadfence();          // acquire

    // ---------------- epilogue (single block, single stage) ----------------
    if (t < 32) {             // S: fixed-order fold over live pairs, warp 0
        float v = 0.0f;
#pragma unroll
        for (int i = 0; i < 13; i++) {
            int idx = t + 32 * i;
            if (idx < 400) {
                int iaa = idx / NGRID;
                int ibb = idx - iaa * NGRID;
                int d   = iaa - ibb;
                if (d >= -DA_MAX && d <= DA_MAX) v += __ldcg(&g_bsum[idx]);
            }
        }
#pragma unroll
        for (int off = 16; off > 0; off >>= 1)
            v += __shfl_xor_sync(0xffffffffu, v, off);
        if (t == 0) sS = v;
    }
    __syncthreads();
    const float k0 = (1.0f / QSCALE) / sS;

    // batched loads first (MLP), then stores + reset
    int q[NGRID];
#pragma unroll
    for (int k = 0; k < NGRID; k++) q[k] = __ldcg(&g_accum[k * 400 + t]);
#pragma unroll
    for (int k = 0; k < NGRID; k++) {
        out[k * 400 + t] = (float)q[k] * k0;
        g_accum[k * 400 + t] = 0;            // replay-safe reset
    }
    __syncthreads();
    if (t == 0) { g_done = 0; __threadfence(); }
}

extern "C" void kernel_launch(void* const* d_in, const int* in_sizes, int n_in,
                              void* d_out, int out_size) {
    const float* space_probs = (const float*)d_in[0];  // 8000 floats
    const float* cov_inv     = (const float*)d_in[1];  // 9 floats
    float* out = (float*)d_out;                        // 8000 floats

    kde_kernel<<<dim3(NGRID, NGRID), 400>>>(space_probs, cov_inv, out);
}

// round 15
// speedup vs baseline: 1.1662x; 1.1662x over previous
#include <cuda_runtime.h>

#define NGRID 20
#define NPTS  8000           // 20^3
#define TD    39             // offsets -19..19
#define DA_MAX 7             // da^2/2 > 28 -> plane pruned
#define D2_CUT 28.0f
#define QSCALE 16777216.0f   // 2^24 fixed point (max sum ~1.8e8 < 2^31)

// Scratch (no allocation allowed in kernel_launch)
__device__ int   g_accum[NPTS];             // fixed-point accumulator
                                            // (zero-init; reset by finish)
__device__ float g_bsum[NGRID * NGRID];     // per live pair sum

// ---------------------------------------------------------------------------
// Kernel A — R13 conv body, frozen. One addition: trigger the programmatic
// launch-completion as soon as this block's results are fenced out, so the
// PDL-launched finish kernel can begin as early as legally possible.
// ---------------------------------------------------------------------------
__global__ void __launch_bounds__(400) conv_kernel(
    const float* __restrict__ p, const float* __restrict__ cov_inv)
{
    __shared__ __align__(16) float sT[TD * TD + 3];
    __shared__ __align__(16) float sp[NGRID * NGRID];
    __shared__ __align__(16) float sred[1600];

    const int t  = threadIdx.x;
    const int ia = blockIdx.x;
    const int ib = blockIdx.y;
    const int da = ia - ib;

    if (da < -DA_MAX || da > DA_MAX) {
        cudaTriggerProgrammaticLaunchCompletion();
        return;
    }

    const float a00 = cov_inv[0], a01 = cov_inv[1], a02 = cov_inv[2];
    const float a11 = cov_inv[4], a12 = cov_inv[5], a22 = cov_inv[8];

    sp[t] = p[ib * 400 + t];

    if (t < 156) {     // table slab via 2-FMUL exp recurrence
        int row = t >> 2, seg = t & 3;
        float dy = (float)(row - 19);
        int   dz0 = -19 + seg * 10;
        int   cnt = (seg == 3) ? 9 : 10;
        float dx = (float)da;
        float c1 = 2.0f * (a02 * dx + a12 * dy);
        float c0 = a00 * dx * dx + 2.0f * a01 * dx * dy + a11 * dy * dy;
        float z  = (float)dz0;
        float g  = expf(-0.5f * (c0 + c1 * z + a22 * z * z));
        float r  = expf(-0.5f * (c1 + a22 * (2.0f * z + 1.0f)));
        float B  = expf(-a22);
        float* dst = &sT[row * TD + (dz0 + 19)];
        for (int i = 0; i < cnt; i++) { dst[i] = g; g *= r; r *= B; }
    }
    __syncthreads();

    const int gidx = t / 100;
    const int s    = t - gidx * 100;
    const int ja   = s / 5;
    const int ka0  = (s - ja * 5) * 4;

    float s00 = a00 - a02 * a02 / a22;
    float s01 = a01 - a02 * a12 / a22;
    float s11 = a11 - a12 * a12 / a22;
    float fx  = (float)da;
    float bq  = s01 * fx;
    float disc = bq * bq - s11 * (s00 * fx * fx - D2_CUT);
    int jb_lo = 0, jb_hi = -1;
    if (disc > 0.0f) {
        float sq  = sqrtf(disc);
        float dyl = (-bq - sq) / s11;
        float dyh = (-bq + sq) / s11;
        jb_lo = max(0,  (int)ceilf ((float)ja - dyh - 0.01f));
        jb_hi = min(19, (int)floorf((float)ja - dyl + 0.01f));
    }

    float acc0 = 0.f, acc1 = 0.f, acc2 = 0.f, acc3 = 0.f;

    for (int jb = jb_lo + gidx; jb <= jb_hi; jb += 4) {
        const float* row = &sT[(ja - jb + 19) * TD];

        float pv[20];
        {
            const float4* pr4 = reinterpret_cast<const float4*>(&sp[jb * NGRID]);
#pragma unroll
            for (int u = 0; u < 5; u++) {
                float4 v = pr4[u];
                pv[4*u] = v.x; pv[4*u+1] = v.y; pv[4*u+2] = v.z; pv[4*u+3] = v.w;
            }
        }

        float w0 = row[ka0 + 19];
        float w1 = row[ka0 + 20];
        float w2 = row[ka0 + 21];
        float w3 = row[ka0 + 22];
#pragma unroll
        for (int kb = 0; kb < 20; kb++) {
            float pvk = pv[kb];
            acc0 = fmaf(w0, pvk, acc0);
            acc1 = fmaf(w1, pvk, acc1);
            acc2 = fmaf(w2, pvk, acc2);
            acc3 = fmaf(w3, pvk, acc3);
            if (kb < 19) { w3 = w2; w2 = w1; w1 = w0; w0 = row[ka0 + 18 - kb]; }
        }
    }

    *reinterpret_cast<float4*>(&sred[gidx * 400 + s * 4]) =
        make_float4(acc0, acc1, acc2, acc3);
    __syncthreads();

    // fold jb-groups (fixed order), accumulate into fixed point (REDG int ->
    // commutative -> bitwise deterministic)
    float val = sred[t] + sred[400 + t] + sred[800 + t] + sred[1200 + t];
    atomicAdd(&g_accum[ia * 400 + t], __float2int_rn(val * QSCALE));
    __syncthreads();

    // block normalizer contribution (deterministic tree)
    sred[t] = val;
    if (t < 112) sred[400 + t] = 0.0f;
    __syncthreads();
    for (int k = 256; k > 32; k >>= 1) {
        if (t < k) sred[t] += sred[t + k];
        __syncthreads();
    }
    if (t < 32) {
        float v = sred[t] + sred[t + 32];
#pragma unroll
        for (int off = 16; off > 0; off >>= 1)
            v += __shfl_down_sync(0xffffffffu, v, off);
        if (t == 0) g_bsum[ia * NGRID + ib] = v;
    }

    __threadfence();                               // results visible
    cudaTriggerProgrammaticLaunchCompletion();     // release PDL dependency
}

// ---------------------------------------------------------------------------
// Kernel B — R13 finish body, launched with PDL so its ramp overlaps conv.
// cudaGridDependencySynchronize() before any read of conv's outputs.
// ---------------------------------------------------------------------------
__global__ void __launch_bounds__(128) finish_kernel(float* __restrict__ out) {
    const int t    = threadIdx.x;
    const int lane = t & 31;
    const int pt   = blockIdx.x * 128 + t;

    cudaGridDependencySynchronize();   // wait for conv completion + visibility

    // issue the accumulator load first (independent of S)
    int q = 0;
    if (pt < NPTS) q = g_accum[pt];

    // warp-redundant fixed-order fold over live (ia,ib) pairs
    float v = 0.0f;
#pragma unroll
    for (int i = 0; i < 13; i++) {               // 13*32 = 416 >= 400
        int idx = lane + 32 * i;
        if (idx < 400) {
            int iaa = idx / NGRID;
            int ibb = idx - iaa * NGRID;
            int d   = iaa - ibb;
            if (d >= -DA_MAX && d <= DA_MAX) v += g_bsum[idx];
        }
    }
#pragma unroll
    for (int off = 16; off > 0; off >>= 1)
        v += __shfl_xor_sync(0xffffffffu, v, off);
    const float S = v;

    if (pt >= NPTS) return;
    out[pt] = (float)q * ((1.0f / QSCALE) / S);
    g_accum[pt] = 0;                              // replay-safe reset
}

extern "C" void kernel_launch(void* const* d_in, const int* in_sizes, int n_in,
                              void* d_out, int out_size) {
    const float* space_probs = (const float*)d_in[0];  // 8000 floats
    const float* cov_inv     = (const float*)d_in[1];  // 9 floats
    float* out = (float*)d_out;                        // 8000 floats

    conv_kernel<<<dim3(NGRID, NGRID), 400>>>(space_probs, cov_inv);

    // Finish with programmatic dependent launch: ramp overlaps conv.
    cudaLaunchConfig_t cfg = {};
    cfg.gridDim  = dim3(64, 1, 1);
    cfg.blockDim = dim3(128, 1, 1);
    cudaLaunchAttribute attrs[1];
    attrs[0].id = cudaLaunchAttributeProgrammaticStreamSerialization;
    attrs[0].val.programmaticStreamSerializationAllowed = 1;
    cfg.attrs    = attrs;
    cfg.numAttrs = 1;
    cudaLaunchKernelEx(&cfg, finish_kernel, out);
}

// round 16
// speedup vs baseline: 1.1693x; 1.0026x over previous
#include <cuda_runtime.h>

#define NGRID 20
#define NPTS  8000           // 20^3
#define TD    39             // offsets -19..19
#define DA_MAX 7             // da^2/2 > 28 -> plane pruned
#define D2_CUT 28.0f
#define QSCALE 16777216.0f   // 2^24 fixed point (max sum ~1.8e8 < 2^31)

// Scratch (no allocation allowed in kernel_launch)
__device__ int   g_accum[NPTS];             // fixed-point accumulator
                                            // (zero-init; reset by finish)
__device__ float g_bsum[NGRID * NGRID];     // per live pair sum (overwritten
                                            // every replay -> no reset needed)

// ---------------------------------------------------------------------------
// Kernel A — conv. Changes vs the 12.2us baseline: __expf on the table-build
// chain, and the block-sum tail done with warp shuffles (1 barrier instead of
// ~7; partial warp 12 handled with an explicit 16-lane mask).
// ---------------------------------------------------------------------------
__global__ void __launch_bounds__(400) conv_kernel(
    const float* __restrict__ p, const float* __restrict__ cov_inv)
{
    __shared__ __align__(16) float sT[TD * TD + 3];
    __shared__ __align__(16) float sp[NGRID * NGRID];
    __shared__ __align__(16) float sred[1600];
    __shared__ float swarp[16];

    const int t  = threadIdx.x;
    const int ia = blockIdx.x;
    const int ib = blockIdx.y;
    const int da = ia - ib;

    if (da < -DA_MAX || da > DA_MAX) {
        cudaTriggerProgrammaticLaunchCompletion();
        return;
    }

    const float a00 = cov_inv[0], a01 = cov_inv[1], a02 = cov_inv[2];
    const float a11 = cov_inv[4], a12 = cov_inv[5], a22 = cov_inv[8];

    sp[t] = p[ib * 400 + t];

    if (t < 156) {     // table slab via 2-FMUL exp recurrence (fast exp)
        int row = t >> 2, seg = t & 3;
        float dy = (float)(row - 19);
        int   dz0 = -19 + seg * 10;
        int   cnt = (seg == 3) ? 9 : 10;
        float dx = (float)da;
        float c1 = 2.0f * (a02 * dx + a12 * dy);
        float c0 = a00 * dx * dx + 2.0f * a01 * dx * dy + a11 * dy * dy;
        float z  = (float)dz0;
        float g  = __expf(-0.5f * (c0 + c1 * z + a22 * z * z));
        float r  = __expf(-0.5f * (c1 + a22 * (2.0f * z + 1.0f)));
        float B  = __expf(-a22);
        float* dst = &sT[row * TD + (dz0 + 19)];
        for (int i = 0; i < cnt; i++) { dst[i] = g; g *= r; r *= B; }
    }
    __syncthreads();

    const int gidx = t / 100;
    const int s    = t - gidx * 100;
    const int ja   = s / 5;
    const int ka0  = (s - ja * 5) * 4;

    float s00 = a00 - a02 * a02 / a22;
    float s01 = a01 - a02 * a12 / a22;
    float s11 = a11 - a12 * a12 / a22;
    float fx  = (float)da;
    float bq  = s01 * fx;
    float disc = bq * bq - s11 * (s00 * fx * fx - D2_CUT);
    int jb_lo = 0, jb_hi = -1;
    if (disc > 0.0f) {
        float sq  = sqrtf(disc);
        float dyl = (-bq - sq) / s11;
        float dyh = (-bq + sq) / s11;
        jb_lo = max(0,  (int)ceilf ((float)ja - dyh - 0.01f));
        jb_hi = min(19, (int)floorf((float)ja - dyl + 0.01f));
    }

    float acc0 = 0.f, acc1 = 0.f, acc2 = 0.f, acc3 = 0.f;

    for (int jb = jb_lo + gidx; jb <= jb_hi; jb += 4) {
        const float* row = &sT[(ja - jb + 19) * TD];

        float pv[20];
        {
            const float4* pr4 = reinterpret_cast<const float4*>(&sp[jb * NGRID]);
#pragma unroll
            for (int u = 0; u < 5; u++) {
                float4 v = pr4[u];
                pv[4*u] = v.x; pv[4*u+1] = v.y; pv[4*u+2] = v.z; pv[4*u+3] = v.w;
            }
        }

        float w0 = row[ka0 + 19];
        float w1 = row[ka0 + 20];
        float w2 = row[ka0 + 21];
        float w3 = row[ka0 + 22];
#pragma unroll
        for (int kb = 0; kb < 20; kb++) {
            float pvk = pv[kb];
            acc0 = fmaf(w0, pvk, acc0);
            acc1 = fmaf(w1, pvk, acc1);
            acc2 = fmaf(w2, pvk, acc2);
            acc3 = fmaf(w3, pvk, acc3);
            if (kb < 19) { w3 = w2; w2 = w1; w1 = w0; w0 = row[ka0 + 18 - kb]; }
        }
    }

    *reinterpret_cast<float4*>(&sred[gidx * 400 + s * 4]) =
        make_float4(acc0, acc1, acc2, acc3);
    __syncthreads();

    // fold jb-groups (fixed order), accumulate into fixed point (int REDG ->
    // commutative -> bitwise deterministic)
    float val = sred[t] + sred[400 + t] + sred[800 + t] + sred[1200 + t];
    atomicAdd(&g_accum[ia * 400 + t], __float2int_rn(val * QSCALE));

    // block normalizer contribution: warp shfl reduce (fixed order), 1 barrier
    {
        const int wid  = t >> 5;          // 0..12 (warp 12 has 16 lanes)
        const int lane = t & 31;
        float wv = val;
        if (wid < 12) {
#pragma unroll
            for (int off = 16; off > 0; off >>= 1)
                wv += __shfl_down_sync(0xffffffffu, wv, off);
        } else {
#pragma unroll
            for (int off = 8; off > 0; off >>= 1)
                wv += __shfl_down_sync(0x0000ffffu, wv, off);
        }
        if (lane == 0) swarp[wid] = wv;
    }
    __syncthreads();
    if (t == 0) {
        float v = 0.0f;
#pragma unroll
        for (int i = 0; i < 13; i++) v += swarp[i];   // fixed order
        g_bsum[ia * NGRID + ib] = v;
    }

    __threadfence();
    cudaTriggerProgrammaticLaunchCompletion();
}

// ---------------------------------------------------------------------------
// Kernel B — finish (unchanged from the 12.2us baseline), PDL-launched.
// ---------------------------------------------------------------------------
__global__ void __launch_bounds__(128) finish_kernel(float* __restrict__ out) {
    const int t    = threadIdx.x;
    const int lane = t & 31;
    const int pt   = blockIdx.x * 128 + t;

    cudaGridDependencySynchronize();

    int q = 0;
    if (pt < NPTS) q = g_accum[pt];

    float v = 0.0f;
#pragma unroll
    for (int i = 0; i < 13; i++) {               // 13*32 = 416 >= 400
        int idx = lane + 32 * i;
        if (idx < 400) {
            int iaa = idx / NGRID;
            int ibb = idx - iaa * NGRID;
            int d   = iaa - ibb;
            if (d >= -DA_MAX && d <= DA_MAX) v += g_bsum[idx];
        }
    }
#pragma unroll
    for (int off = 16; off > 0; off >>= 1)
        v += __shfl_xor_sync(0xffffffffu, v, off);
    const float S = v;

    if (pt >= NPTS) return;
    out[pt] = (float)q * ((1.0f / QSCALE) / S);
    g_accum[pt] = 0;                              // replay-safe reset
}

extern "C" void kernel_launch(void* const* d_in, const int* in_sizes, int n_in,
                              void* d_out, int out_size) {
    const float* space_probs = (const float*)d_in[0];  // 8000 floats
    const float* cov_inv     = (const float*)d_in[1];  // 9 floats
    float* out = (float*)d_out;                        // 8000 floats

    conv_kernel<<<dim3(NGRID, NGRID), 400>>>(space_probs, cov_inv);

    cudaLaunchConfig_t cfg = {};
    cfg.gridDim  = dim3(64, 1, 1);
    cfg.blockDim = dim3(128, 1, 1);
    cudaLaunchAttribute attrs[1];
    attrs[0].id = cudaLaunchAttributeProgrammaticStreamSerialization;
    attrs[0].val.programmaticStreamSerializationAllowed = 1;
    cfg.attrs    = attrs;
    cfg.numAttrs = 1;
    cudaLaunchKernelEx(&cfg, finish_kernel, out);
}